// round 14
// baseline (speedup 1.0000x reference)
#include <cuda_runtime.h>

// Problem constants (fixed by the reference: S=256, B=256, D=1024, MAX_LEN=256)
#define S_DIM 256
#define B_DIM 256
#define D_DIM 1024
#define DV    (D_DIM / 4)   // 256 float4 per row
#define B_PER_BLOCK 32

// Device scratch (no allocations allowed in kernel_launch).
// g_pec[s*D + d] = pe[s,d] + b_xy[d] + b_seg[d]   (1 MB)
// g_w0/g_w1 = de-interleaved W_xy columns, g_ws = W_seg[:,0]   (12 KB)
__device__ float  g_pec[S_DIM * D_DIM];
__device__ float4 g_w0[DV];
__device__ float4 g_w1[DV];
__device__ float4 g_ws[DV];

// ---------------------------------------------------------------------------
// Prep: fold biases + pe, de-interleave weights. grid = S_DIM, block = 256.
// Each thread handles one float4 of d for its s.
// ---------------------------------------------------------------------------
__global__ __launch_bounds__(256) void pe_prep_kernel(
    const float* __restrict__ W_xy,   // [D,2] interleaved
    const float* __restrict__ b_xy,   // [D]
    const float* __restrict__ W_seg,  // [D,1]
    const float* __restrict__ b_seg,  // [D]
    const float* __restrict__ pe)     // [MAX_LEN,1,D]
{
    const int s  = blockIdx.x;
    const int tv = threadIdx.x;          // float4 index along d
    const int d  = tv * 4;

    float4 p  = *reinterpret_cast<const float4*>(pe   + (size_t)s * D_DIM + d);
    float4 bx = *reinterpret_cast<const float4*>(b_xy + d);
    float4 bs = *reinterpret_cast<const float4*>(b_seg + d);

    float4 r;
    r.x = p.x + bx.x + bs.x;
    r.y = p.y + bx.y + bs.y;
    r.z = p.z + bx.z + bs.z;
    r.w = p.w + bx.w + bs.w;
    *reinterpret_cast<float4*>(g_pec + (size_t)s * D_DIM + d) = r;

    if (s == 0) {
        // W_xy rows d..d+3, 2 floats each = 8 contiguous floats (32B-aligned)
        float4 a = *reinterpret_cast<const float4*>(W_xy + 2 * d);
        float4 b = *reinterpret_cast<const float4*>(W_xy + 2 * d + 4);
        float4 w0, w1;
        w0.x = a.x; w1.x = a.y;   // row d
        w0.y = a.z; w1.y = a.w;   // row d+1
        w0.z = b.x; w1.z = b.y;   // row d+2
        w0.w = b.z; w1.w = b.w;   // row d+3
        g_w0[tv] = w0;
        g_w1[tv] = w1;
        g_ws[tv] = *reinterpret_cast<const float4*>(W_seg + d);
    }
}

// ---------------------------------------------------------------------------
// Main: grid = (S_DIM, B_DIM / B_PER_BLOCK), block = 256.
// Each block: one s, 32 consecutive b. Per-d operands live in registers for
// all 32 iterations; inner loop = 3 broadcast scalar loads + 12 FMA + 1 STG.128.
// ---------------------------------------------------------------------------
__global__ __launch_bounds__(256) void pe_main_kernel(
    const float* __restrict__ x,      // [S,B,3]
    float* __restrict__ out)          // [S,B,D]
{
    const int s  = blockIdx.x;
    const int b0 = blockIdx.y * B_PER_BLOCK;
    const int tv = threadIdx.x;       // float4 index along d

    const float4 w0 = g_w0[tv];
    const float4 w1 = g_w1[tv];
    const float4 ws = g_ws[tv];
    const float4 pc = reinterpret_cast<const float4*>(g_pec + (size_t)s * D_DIM)[tv];

    const float* xp = x + ((size_t)s * B_DIM + b0) * 3;
    float4* op = reinterpret_cast<float4*>(out) + ((size_t)s * B_DIM + b0) * DV + tv;

#pragma unroll 4
    for (int i = 0; i < B_PER_BLOCK; ++i) {
        const float x0 = __ldg(xp + 0);
        const float x1 = __ldg(xp + 1);
        const float x2 = __ldg(xp + 2);

        float4 r;
        r.x = fmaf(x0, w0.x, fmaf(x1, w1.x, fmaf(x2, ws.x, pc.x)));
        r.y = fmaf(x0, w0.y, fmaf(x1, w1.y, fmaf(x2, ws.y, pc.y)));
        r.z = fmaf(x0, w0.z, fmaf(x1, w1.z, fmaf(x2, ws.z, pc.z)));
        r.w = fmaf(x0, w0.w, fmaf(x1, w1.w, fmaf(x2, ws.w, pc.w)));

        // Streaming store: output is never re-read, don't pollute L2.
        __stcs(op, r);

        xp += 3;
        op += DV;
    }
}

// ---------------------------------------------------------------------------
// Harness entry. Input order per metadata: x, W_xy, b_xy, W_seg, b_seg, pe.
// ---------------------------------------------------------------------------
extern "C" void kernel_launch(void* const* d_in, const int* in_sizes, int n_in,
                              void* d_out, int out_size)
{
    const float* x     = (const float*)d_in[0];
    const float* W_xy  = (const float*)d_in[1];
    const float* b_xy  = (const float*)d_in[2];
    const float* W_seg = (const float*)d_in[3];
    const float* b_seg = (const float*)d_in[4];
    const float* pe    = (const float*)d_in[5];
    float* out = (float*)d_out;

    pe_prep_kernel<<<S_DIM, 256>>>(W_xy, b_xy, W_seg, b_seg, pe);

    dim3 grid(S_DIM, B_DIM / B_PER_BLOCK);
    pe_main_kernel<<<grid, 256>>>(x, out);
}

// round 15
// speedup vs baseline: 1.0757x; 1.0757x over previous
#include <cuda_runtime.h>

// Problem constants (fixed by the reference: S=256, B=256, D=1024, MAX_LEN=256)
#define S_DIM 256
#define B_DIM 256
#define D_DIM 1024
#define DV    (D_DIM / 4)   // 256 float4 per row
#define BPB   64            // batch elements per block

// Single fused kernel.
//   grid = (S_DIM, B_DIM / BPB) = (256, 4), block = 256 threads.
//   Each block owns one s and 64 consecutive b.
//   Per-thread (one float4 of d): de-interleave W_xy, fold pe+b_xy+b_seg,
//   all from L2-resident broadcast loads, amortized over 64 iterations.
//   x tile for the block (192 floats) staged in shared memory once; the
//   hot loop is 3 broadcast LDS + 12 FMA + 1 STG.128 streaming store, so
//   L1tex does essentially only the store wavefronts.
__global__ __launch_bounds__(256) void pe_fused_kernel(
    const float* __restrict__ x,      // [S,B,3]
    const float* __restrict__ W_xy,   // [D,2] interleaved
    const float* __restrict__ b_xy,   // [D]
    const float* __restrict__ W_seg,  // [D,1]
    const float* __restrict__ b_seg,  // [D]
    const float* __restrict__ pe,     // [MAX_LEN,1,D]
    float* __restrict__ out)          // [S,B,D]
{
    __shared__ float s_x[BPB * 3];    // 768 B

    const int s  = blockIdx.x;
    const int b0 = blockIdx.y * BPB;
    const int tv = threadIdx.x;       // float4 index along d
    const int d  = tv * 4;

    // Stage this block's x slice: 192 contiguous floats.
    if (tv < BPB * 3)
        s_x[tv] = x[((size_t)s * B_DIM + b0) * 3 + tv];

    // Per-thread setup (L2-hit broadcast loads, once per 64 stores).
    // W_xy rows d..d+3, 2 floats each = 8 contiguous floats (32B-aligned).
    const float4 a  = *reinterpret_cast<const float4*>(W_xy + 2 * d);
    const float4 bq = *reinterpret_cast<const float4*>(W_xy + 2 * d + 4);
    const float4 w0 = make_float4(a.x, a.z, bq.x, bq.z);   // column 0
    const float4 w1 = make_float4(a.y, a.w, bq.y, bq.w);   // column 1
    const float4 ws = *reinterpret_cast<const float4*>(W_seg + d);

    const float4 p  = *reinterpret_cast<const float4*>(pe    + (size_t)s * D_DIM + d);
    const float4 bx = *reinterpret_cast<const float4*>(b_xy  + d);
    const float4 bs = *reinterpret_cast<const float4*>(b_seg + d);
    const float4 pc = make_float4(p.x + bx.x + bs.x,
                                  p.y + bx.y + bs.y,
                                  p.z + bx.z + bs.z,
                                  p.w + bx.w + bs.w);

    __syncthreads();

    float4* op = reinterpret_cast<float4*>(out)
               + ((size_t)s * B_DIM + b0) * DV + tv;

#pragma unroll 4
    for (int i = 0; i < BPB; ++i) {
        const float x0 = s_x[3 * i + 0];   // broadcast LDS, conflict-free
        const float x1 = s_x[3 * i + 1];
        const float x2 = s_x[3 * i + 2];

        float4 r;
        r.x = fmaf(x0, w0.x, fmaf(x1, w1.x, fmaf(x2, ws.x, pc.x)));
        r.y = fmaf(x0, w0.y, fmaf(x1, w1.y, fmaf(x2, ws.y, pc.y)));
        r.z = fmaf(x0, w0.z, fmaf(x1, w1.z, fmaf(x2, ws.z, pc.z)));
        r.w = fmaf(x0, w0.w, fmaf(x1, w1.w, fmaf(x2, ws.w, pc.w)));

        // Streaming store: output is never re-read, don't pollute L2.
        __stcs(op, r);
        op += DV;
    }
}

// ---------------------------------------------------------------------------
// Harness entry. Input order per metadata: x, W_xy, b_xy, W_seg, b_seg, pe.
// ---------------------------------------------------------------------------
extern "C" void kernel_launch(void* const* d_in, const int* in_sizes, int n_in,
                              void* d_out, int out_size)
{
    const float* x     = (const float*)d_in[0];
    const float* W_xy  = (const float*)d_in[1];
    const float* b_xy  = (const float*)d_in[2];
    const float* W_seg = (const float*)d_in[3];
    const float* b_seg = (const float*)d_in[4];
    const float* pe    = (const float*)d_in[5];
    float* out = (float*)d_out;

    dim3 grid(S_DIM, B_DIM / BPB);
    pe_fused_kernel<<<grid, 256>>>(x, W_xy, b_xy, W_seg, b_seg, pe, out);
}